// round 1
// baseline (speedup 1.0000x reference)
#include <cuda_runtime.h>
#include <cstdint>

#define NTOK  64
#define HID   2048
#define INTER 1408
#define NEXP  32
#define TOPK  4
#define NASS  (NTOK*TOPK)

typedef unsigned long long ull;

// ---------------- scratch (no allocation allowed) ----------------
__device__ int   g_cnt[NEXP];
__device__ int   g_off[NEXP];
__device__ int   g_tok[NASS];          // token id per assignment (bucketed by expert)
__device__ float g_wass[NASS];         // routing weight per assignment
__device__ int   g_aidx[NASS];         // [t][j] -> assignment slot
__device__ float g_mixed[(size_t)NASS*INTER];  // silu(gate)*up per assignment
__device__ float g_part [(size_t)NASS*HID];    // weighted down-proj per assignment

// ---------------- f32x2 packed FMA (sm_100+) ----------------
__device__ __forceinline__ void fma2(ull &a, ull b, ull c) {
    asm("fma.rn.f32x2 %0, %1, %2, %0;" : "+l"(a) : "l"(b), "l"(c));
}
__device__ __forceinline__ float hsum(ull a) {
    float lo = __uint_as_float((unsigned)a);
    float hi = __uint_as_float((unsigned)(a >> 32));
    float s = lo + hi;
    #pragma unroll
    for (int o = 16; o > 0; o >>= 1) s += __shfl_xor_sync(0xffffffffu, s, o);
    return s;
}

// ---------------- 1) routing: top-4 + softmax + deterministic buckets ----------------
__global__ void route_k(const float* __restrict__ logits) {
    __shared__ int   s_ids[NTOK][TOPK];
    __shared__ float s_w  [NTOK][TOPK];
    __shared__ int   s_cnt[NEXP];
    __shared__ int   s_off[NEXP];
    int t = threadIdx.x;  // 64 threads

    float v[NEXP];
    #pragma unroll
    for (int e = 0; e < NEXP; e++) v[e] = logits[t*NEXP + e];

    int ids[TOPK]; float vals[TOPK];
    #pragma unroll
    for (int j = 0; j < TOPK; j++) {
        int bi = 0; float bv = -1e30f;
        #pragma unroll
        for (int e = 0; e < NEXP; e++) if (v[e] > bv) { bv = v[e]; bi = e; }
        ids[j] = bi; vals[j] = bv; v[bi] = -1e30f;
    }
    float m = vals[0], s = 0.f, w[TOPK];
    #pragma unroll
    for (int j = 0; j < TOPK; j++) { w[j] = __expf(vals[j] - m); s += w[j]; }
    float inv = 1.f / s;
    #pragma unroll
    for (int j = 0; j < TOPK; j++) { w[j] *= inv; s_ids[t][j] = ids[j]; s_w[t][j] = w[j]; }
    __syncthreads();

    if (t < NEXP) {
        int c = 0;
        for (int tt = 0; tt < NTOK; tt++)
            #pragma unroll
            for (int jj = 0; jj < TOPK; jj++) if (s_ids[tt][jj] == t) c++;
        s_cnt[t] = c;
    }
    __syncthreads();
    if (t < NEXP) {
        int o = 0;
        for (int e = 0; e < t; e++) o += s_cnt[e];
        s_off[t] = o; g_cnt[t] = s_cnt[t]; g_off[t] = o;
    }
    __syncthreads();

    // deterministic rank: number of earlier tokens choosing the same expert
    #pragma unroll
    for (int j = 0; j < TOPK; j++) {
        int e = s_ids[t][j];
        int r = 0;
        for (int tt = 0; tt < t; tt++)
            #pragma unroll
            for (int jj = 0; jj < TOPK; jj++) if (s_ids[tt][jj] == e) r++;
        int slot = s_off[e] + r;
        g_tok[slot]  = t;
        g_wass[slot] = s_w[t][j];
        g_aidx[t*TOPK + j] = slot;
    }
}

// ---------------- 2) gate/up GEMM: M=cnt, N=1408, K=2048 ----------------
// block = (row_tile 128, expert). 8 warps; warp owns 8 row-pairs (TN=2).
// x tile (<=16 tokens) lives in smem as ulonglong2[slot][512].
#define GU_ROWS_BLK 128
#define GU_TILES    (INTER / GU_ROWS_BLK)   // 11

template<int TM>
__device__ __forceinline__ void gu_rows(const float* __restrict__ wg_e,
                                        const float* __restrict__ wu_e,
                                        const ulonglong2* __restrict__ xs,
                                        int row0, int slot0, int rem)
{
    const int warp = threadIdx.x >> 5, lane = threadIdx.x & 31;
    for (int rp = 0; rp < 8; rp++) {
        int row = row0 + warp * 16 + rp * 2;
        const ulonglong2* g0 = reinterpret_cast<const ulonglong2*>(wg_e + (size_t)row    * HID);
        const ulonglong2* g1 = reinterpret_cast<const ulonglong2*>(wg_e + (size_t)(row+1)* HID);
        const ulonglong2* u0 = reinterpret_cast<const ulonglong2*>(wu_e + (size_t)row    * HID);
        const ulonglong2* u1 = reinterpret_cast<const ulonglong2*>(wu_e + (size_t)(row+1)* HID);
        ull ag0[TM], ag1[TM], au0[TM], au1[TM];
        #pragma unroll
        for (int t = 0; t < TM; t++) { ag0[t]=0ull; ag1[t]=0ull; au0[t]=0ull; au1[t]=0ull; }
        #pragma unroll 4
        for (int i = 0; i < 16; i++) {
            int o = lane + (i << 5);
            ulonglong2 a0 = g0[o], a1 = g1[o], b0 = u0[o], b1 = u1[o];
            #pragma unroll
            for (int t = 0; t < TM; t++) {
                ulonglong2 xv = xs[t * 512 + o];
                fma2(ag0[t], a0.x, xv.x); fma2(ag0[t], a0.y, xv.y);
                fma2(ag1[t], a1.x, xv.x); fma2(ag1[t], a1.y, xv.y);
                fma2(au0[t], b0.x, xv.x); fma2(au0[t], b0.y, xv.y);
                fma2(au1[t], b1.x, xv.x); fma2(au1[t], b1.y, xv.y);
            }
        }
        #pragma unroll
        for (int t = 0; t < TM; t++) {
            float gA = hsum(ag0[t]);
            float gB = hsum(ag1[t]);
            float uA = hsum(au0[t]);
            float uB = hsum(au1[t]);
            if (lane == t && t < rem) {
                float sA = gA * __frcp_rn(1.f + __expf(-gA));
                float sB = gB * __frcp_rn(1.f + __expf(-gB));
                float* mp = g_mixed + (size_t)(slot0 + t) * INTER;
                mp[row]     = sA * uA;
                mp[row + 1] = sB * uB;
            }
        }
    }
}

__global__ void __launch_bounds__(256, 1) gateup_k(const float* __restrict__ x,
                                                   const float* __restrict__ wg,
                                                   const float* __restrict__ wu)
{
    extern __shared__ ulonglong2 sh[];
    int e = blockIdx.y;
    int cnt = g_cnt[e];
    if (cnt == 0) return;
    int base = g_off[e];
    int row0 = blockIdx.x * GU_ROWS_BLK;
    const float* wg_e = wg + (size_t)e * INTER * HID;
    const float* wu_e = wu + (size_t)e * INTER * HID;

    for (int s0 = 0; s0 < cnt; s0 += 16) {
        int rem = cnt - s0; if (rem > 16) rem = 16;
        int tmv = rem <= 4 ? 4 : rem <= 8 ? 8 : rem <= 12 ? 12 : 16;
        __syncthreads();
        for (int idx = threadIdx.x; idx < tmv * 512; idx += 256) {
            int slot = idx >> 9, j = idx & 511;
            ulonglong2 v;
            if (slot < rem) {
                int tok = g_tok[base + s0 + slot];
                v = reinterpret_cast<const ulonglong2*>(x + (size_t)tok * HID)[j];
            } else { v.x = 0ull; v.y = 0ull; }
            sh[idx] = v;
        }
        __syncthreads();
        if      (tmv == 4 ) gu_rows<4 >(wg_e, wu_e, sh, row0, base + s0, rem);
        else if (tmv == 8 ) gu_rows<8 >(wg_e, wu_e, sh, row0, base + s0, rem);
        else if (tmv == 12) gu_rows<12>(wg_e, wu_e, sh, row0, base + s0, rem);
        else                gu_rows<16>(wg_e, wu_e, sh, row0, base + s0, rem);
    }
}

// ---------------- 3) down GEMM: M=cnt, N=2048, K=1408 ----------------
// block = (row_tile 128, expert). warp owns 4 row-quads (TN=4).
#define DN_ROWS_BLK 128
#define DN_TILES    (HID / DN_ROWS_BLK)   // 16

template<int TM>
__device__ __forceinline__ void dn_rows(const float* __restrict__ wd_e,
                                        const ulonglong2* __restrict__ xs,
                                        int row0, int slot0, int rem)
{
    const int warp = threadIdx.x >> 5, lane = threadIdx.x & 31;
    for (int q = 0; q < 4; q++) {
        int row = row0 + warp * 16 + q * 4;
        const ulonglong2* d0 = reinterpret_cast<const ulonglong2*>(wd_e + (size_t)(row  ) * INTER);
        const ulonglong2* d1 = reinterpret_cast<const ulonglong2*>(wd_e + (size_t)(row+1) * INTER);
        const ulonglong2* d2 = reinterpret_cast<const ulonglong2*>(wd_e + (size_t)(row+2) * INTER);
        const ulonglong2* d3 = reinterpret_cast<const ulonglong2*>(wd_e + (size_t)(row+3) * INTER);
        ull a0[TM], a1[TM], a2[TM], a3[TM];
        #pragma unroll
        for (int t = 0; t < TM; t++) { a0[t]=0ull; a1[t]=0ull; a2[t]=0ull; a3[t]=0ull; }
        #pragma unroll
        for (int i = 0; i < 11; i++) {   // 1408/4 = 352 = 32*11
            int o = lane + (i << 5);
            ulonglong2 w0 = d0[o], w1 = d1[o], w2 = d2[o], w3 = d3[o];
            #pragma unroll
            for (int t = 0; t < TM; t++) {
                ulonglong2 xv = xs[t * 352 + o];
                fma2(a0[t], w0.x, xv.x); fma2(a0[t], w0.y, xv.y);
                fma2(a1[t], w1.x, xv.x); fma2(a1[t], w1.y, xv.y);
                fma2(a2[t], w2.x, xv.x); fma2(a2[t], w2.y, xv.y);
                fma2(a3[t], w3.x, xv.x); fma2(a3[t], w3.y, xv.y);
            }
        }
        #pragma unroll
        for (int t = 0; t < TM; t++) {
            float s0v = hsum(a0[t]);
            float s1v = hsum(a1[t]);
            float s2v = hsum(a2[t]);
            float s3v = hsum(a3[t]);
            if (lane == t && t < rem) {
                float w = g_wass[slot0 + t];
                float* pp = g_part + (size_t)(slot0 + t) * HID;
                pp[row]     = s0v * w;
                pp[row + 1] = s1v * w;
                pp[row + 2] = s2v * w;
                pp[row + 3] = s3v * w;
            }
        }
    }
}

__global__ void __launch_bounds__(256, 1) down_k(const float* __restrict__ wd)
{
    extern __shared__ ulonglong2 sh[];
    int e = blockIdx.y;
    int cnt = g_cnt[e];
    if (cnt == 0) return;
    int base = g_off[e];
    int row0 = blockIdx.x * DN_ROWS_BLK;
    const float* wd_e = wd + (size_t)e * HID * INTER;

    for (int s0 = 0; s0 < cnt; s0 += 16) {
        int rem = cnt - s0; if (rem > 16) rem = 16;
        int tmv = rem <= 4 ? 4 : rem <= 8 ? 8 : rem <= 12 ? 12 : 16;
        __syncthreads();
        for (int idx = threadIdx.x; idx < tmv * 352; idx += 256) {
            int slot = idx / 352, j = idx - slot * 352;
            ulonglong2 v;
            if (slot < rem) {
                v = reinterpret_cast<const ulonglong2*>(g_mixed + (size_t)(base + s0 + slot) * INTER)[j];
            } else { v.x = 0ull; v.y = 0ull; }
            sh[idx] = v;
        }
        __syncthreads();
        if      (tmv == 4 ) dn_rows<4 >(wd_e, sh, row0, base + s0, rem);
        else if (tmv == 8 ) dn_rows<8 >(wd_e, sh, row0, base + s0, rem);
        else if (tmv == 12) dn_rows<12>(wd_e, sh, row0, base + s0, rem);
        else                dn_rows<16>(wd_e, sh, row0, base + s0, rem);
    }
}

// ---------------- 4) gather: out[t,h] = sum_j part[aidx[t][j]][h] ----------------
__global__ void gather_k(float* __restrict__ out)
{
    int idx = blockIdx.x * 256 + threadIdx.x;     // 131072 total
    int t = idx >> 11;
    int h = idx & 2047;
    const int* ai = g_aidx + t * TOPK;
    float s = 0.f;
    #pragma unroll
    for (int j = 0; j < TOPK; j++) s += g_part[(size_t)ai[j] * HID + h];
    out[idx] = s;
}

// ---------------- launch ----------------
extern "C" void kernel_launch(void* const* d_in, const int* in_sizes, int n_in,
                              void* d_out, int out_size)
{
    const float* x      = (const float*)d_in[0];
    const float* logits = (const float*)d_in[1];
    const float* wg     = (const float*)d_in[2];
    const float* wu     = (const float*)d_in[3];
    const float* wd     = (const float*)d_in[4];
    float* out = (float*)d_out;

    const int GU_SMEM = 16 * 512 * (int)sizeof(ulonglong2);   // 131072
    const int DN_SMEM = 16 * 352 * (int)sizeof(ulonglong2);   // 90112
    cudaFuncSetAttribute(gateup_k, cudaFuncAttributeMaxDynamicSharedMemorySize, GU_SMEM);
    cudaFuncSetAttribute(down_k,   cudaFuncAttributeMaxDynamicSharedMemorySize, DN_SMEM);

    route_k<<<1, NTOK>>>(logits);
    gateup_k<<<dim3(GU_TILES, NEXP), 256, GU_SMEM>>>(x, wg, wu);
    down_k  <<<dim3(DN_TILES, NEXP), 256, DN_SMEM>>>(wd);
    gather_k<<<(NTOK * HID) / 256, 256>>>(out);
}